// round 3
// baseline (speedup 1.0000x reference)
#include <cuda_runtime.h>
#include <cuda_bf16.h>
#include <cstdint>

#define B_   16
#define TQ_  128
#define TK_  256
#define DIN_ 64
#define H_   256
#define DV_  256
#define IT_  8
#define NEGV (-1000000.0f)

// Scratch for projected q/k (static device arrays: allocation-free).
__device__ float g_q[B_ * TQ_ * H_];   // [B, Tq, H]
__device__ float g_k[B_ * TK_ * H_];   // [B, Tk, H]

__device__ __forceinline__ float fast_tanh(float x) {
    float y;
    asm("tanh.approx.f32 %0, %1;" : "=f"(y) : "f"(x));
    return y;
}

// ---------------------------------------------------------------------------
// Kernel 1: projections  g_q = queries @ wq,  g_k = keys @ wk
// Each block: 32 rows. Thread t owns output column h=t; holds W[:,t] (64
// values) in registers, streams 32 input rows from SMEM (broadcast LDS.128).
// ---------------------------------------------------------------------------
__global__ __launch_bounds__(256) void proj_kernel(
    const float* __restrict__ queries, const float* __restrict__ keys,
    const float* __restrict__ wq, const float* __restrict__ wk)
{
    constexpr int RPB = 32;
    int blk = blockIdx.x;
    const float* X; const float* W; float* Y; int row0;
    constexpr int QBLKS = (B_ * TQ_) / RPB;   // 64
    if (blk < QBLKS) { X = queries; W = wq; Y = g_q; row0 = blk * RPB; }
    else             { X = keys;    W = wk; Y = g_k; row0 = (blk - QBLKS) * RPB; }

    const int tid = threadIdx.x;

    float w[DIN_];
    #pragma unroll
    for (int d = 0; d < DIN_; d++) w[d] = W[d * H_ + tid];   // coalesced

    __shared__ __align__(16) float s_x[RPB][DIN_];           // 8 KB
    const float* xb = X + (size_t)row0 * DIN_;
    #pragma unroll
    for (int k = 0; k < (RPB * DIN_) / 256; k++)
        ((float*)s_x)[tid + k * 256] = xb[tid + k * 256];
    __syncthreads();

    #pragma unroll 4
    for (int r = 0; r < RPB; r++) {
        const float4* xr = (const float4*)s_x[r];
        float acc = 0.f;
        #pragma unroll
        for (int d4 = 0; d4 < DIN_ / 4; d4++) {
            float4 xv = xr[d4];
            acc += xv.x * w[d4 * 4 + 0];
            acc += xv.y * w[d4 * 4 + 1];
            acc += xv.z * w[d4 * 4 + 2];
            acc += xv.w * w[d4 * 4 + 3];
        }
        Y[(size_t)(row0 + r) * H_ + tid] = acc;
    }
}

// ---------------------------------------------------------------------------
// Kernel 2: fused scores + masked softmax + attn@V.
// One CTA = (batch b, tile of IT_=8 query rows). 256 threads.
//   Phase 1: thread t owns key row j=t; accumulates 8 scores (one per query)
//            while streaming k[b,t,:] as float4 (L2-resident) and reading
//            q/wv via SMEM broadcast.
//   Softmax: warp w owns row i=w (8 warps = 8 rows), in-SMEM.
//   Phase 2: thread t owns output column v=t; coalesced values loads.
// ---------------------------------------------------------------------------
__global__ __launch_bounds__(256, 2) void attn_kernel(
    const float* __restrict__ values, const int* __restrict__ valid_lens,
    const float* __restrict__ wv, float* __restrict__ out)
{
    const int b  = blockIdx.x >> 4;          // 16 q-tiles per batch
    const int i0 = (blockIdx.x & 15) * IT_;
    const int tid = threadIdx.x;

    __shared__ __align__(16) float s_q[IT_][H_];    // 8 KB
    __shared__ __align__(16) float s_wv[H_];        // 1 KB
    __shared__ __align__(16) float s_sc[IT_][TK_];  // 8 KB (scores -> attn)

    s_wv[tid] = wv[tid];
    #pragma unroll
    for (int i = 0; i < IT_; i++)
        s_q[i][tid] = g_q[((size_t)b * TQ_ + i0 + i) * H_ + tid];
    const int vl = valid_lens[b];
    __syncthreads();

    // ---- Phase 1: additive-attention scores (MUFU.TANH-bound) ----
    const float4* krow = (const float4*)(g_k + ((size_t)b * TK_ + tid) * H_);
    float acc[IT_];
    #pragma unroll
    for (int i = 0; i < IT_; i++) acc[i] = 0.f;

    #pragma unroll 2
    for (int h4 = 0; h4 < H_ / 4; h4++) {
        float4 kv  = krow[h4];
        float4 wvv = ((const float4*)s_wv)[h4];
        #pragma unroll
        for (int i = 0; i < IT_; i++) {
            float4 qv = ((const float4*)s_q[i])[h4];
            acc[i] += wvv.x * fast_tanh(qv.x + kv.x);
            acc[i] += wvv.y * fast_tanh(qv.y + kv.y);
            acc[i] += wvv.z * fast_tanh(qv.z + kv.z);
            acc[i] += wvv.w * fast_tanh(qv.w + kv.w);
        }
    }
    #pragma unroll
    for (int i = 0; i < IT_; i++)
        s_sc[i][tid] = (tid < vl) ? acc[i] : NEGV;
    __syncthreads();

    // ---- Masked softmax: warp w handles row i=w ----
    {
        const int i = tid >> 5, lane = tid & 31;
        float v[TK_ / 32];
        float m = -3.402823466e38f;
        #pragma unroll
        for (int k = 0; k < TK_ / 32; k++) {
            v[k] = s_sc[i][lane + k * 32];
            m = fmaxf(m, v[k]);
        }
        #pragma unroll
        for (int off = 16; off; off >>= 1)
            m = fmaxf(m, __shfl_xor_sync(0xffffffffu, m, off));
        float sum = 0.f;
        #pragma unroll
        for (int k = 0; k < TK_ / 32; k++) {
            v[k] = __expf(v[k] - m);
            sum += v[k];
        }
        #pragma unroll
        for (int off = 16; off; off >>= 1)
            sum += __shfl_xor_sync(0xffffffffu, sum, off);
        const float inv = 1.0f / sum;
        #pragma unroll
        for (int k = 0; k < TK_ / 32; k++)
            s_sc[i][lane + k * 32] = v[k] * inv;
    }
    __syncthreads();

    // ---- Phase 2: out = attn @ values (coalesced values loads) ----
    const float* vbase = values + (size_t)b * TK_ * DV_ + tid;
    float oacc[IT_];
    #pragma unroll
    for (int i = 0; i < IT_; i++) oacc[i] = 0.f;

    #pragma unroll 2
    for (int j4 = 0; j4 < TK_ / 4; j4++) {
        float v0 = vbase[(j4 * 4 + 0) * DV_];
        float v1 = vbase[(j4 * 4 + 1) * DV_];
        float v2 = vbase[(j4 * 4 + 2) * DV_];
        float v3 = vbase[(j4 * 4 + 3) * DV_];
        #pragma unroll
        for (int i = 0; i < IT_; i++) {
            float4 a = ((const float4*)s_sc[i])[j4];
            oacc[i] += a.x * v0;
            oacc[i] += a.y * v1;
            oacc[i] += a.z * v2;
            oacc[i] += a.w * v3;
        }
    }
    #pragma unroll
    for (int i = 0; i < IT_; i++)
        out[((size_t)b * TQ_ + i0 + i) * DV_ + tid] = oacc[i];
}

extern "C" void kernel_launch(void* const* d_in, const int* in_sizes, int n_in,
                              void* d_out, int out_size)
{
    const float* queries    = (const float*)d_in[0];
    const float* keys       = (const float*)d_in[1];
    const float* values     = (const float*)d_in[2];
    const int*   valid_lens = (const int*)d_in[3];
    const float* wq         = (const float*)d_in[4];
    const float* wk         = (const float*)d_in[5];
    const float* wv         = (const float*)d_in[6];
    float*       out        = (float*)d_out;

    const int proj_blocks = (B_ * TQ_ + B_ * TK_) / 32;       // 192
    proj_kernel<<<proj_blocks, 256>>>(queries, keys, wq, wk);
    attn_kernel<<<(B_ * TQ_) / IT_, 256>>>(values, valid_lens, wv, out);
}